// round 12
// baseline (speedup 1.0000x reference)
#include <cuda_runtime.h>

// Y: [16384, 2048] fp32, row-major.
// loss = sum_d | 1 - (sum_n Y[n,d]^2) / n |

#define N_ROWS        16384
#define N_COLS        2048
#define COLS4         (N_COLS / 4)               // 512 float4 per row
#define ROWS_PER_SLAB 8
#define N_SLABS       (N_ROWS / ROWS_PER_SLAB)   // 2048 slabs
#define GRID1         148                        // 1 block per SM: co-residency
                                                 // guaranteed with 512 threads,
                                                 // NO register cap needed.
#define SLAB_BASE     (N_SLABS / GRID1)          // 13
#define SLAB_REM      (N_SLABS % GRID1)          // first 124 blocks take 14

// Scratch (no cudaMalloc allowed): per-block partial column sums.
__device__ float4       g_partial[GRID1 * COLS4];
__device__ unsigned int g_done;    // phase-1 arrival counter
__device__ unsigned int g_done2;   // completion counter (for reset)

#define SQACC8(P)                                                   \
    do {                                                            \
        float4 u0 = (P)[0 * COLS4];                                 \
        float4 u1 = (P)[1 * COLS4];                                 \
        float4 u2 = (P)[2 * COLS4];                                 \
        float4 u3 = (P)[3 * COLS4];                                 \
        float4 u4 = (P)[4 * COLS4];                                 \
        float4 u5 = (P)[5 * COLS4];                                 \
        float4 u6 = (P)[6 * COLS4];                                 \
        float4 u7 = (P)[7 * COLS4];                                 \
        ax = fmaf(u0.x, u0.x, ax); ay = fmaf(u0.y, u0.y, ay);       \
        az = fmaf(u0.z, u0.z, az); aw = fmaf(u0.w, u0.w, aw);       \
        ax = fmaf(u1.x, u1.x, ax); ay = fmaf(u1.y, u1.y, ay);       \
        az = fmaf(u1.z, u1.z, az); aw = fmaf(u1.w, u1.w, aw);       \
        ax = fmaf(u2.x, u2.x, ax); ay = fmaf(u2.y, u2.y, ay);       \
        az = fmaf(u2.z, u2.z, az); aw = fmaf(u2.w, u2.w, aw);       \
        ax = fmaf(u3.x, u3.x, ax); ay = fmaf(u3.y, u3.y, ay);       \
        az = fmaf(u3.z, u3.z, az); aw = fmaf(u3.w, u3.w, aw);       \
        ax = fmaf(u4.x, u4.x, ax); ay = fmaf(u4.y, u4.y, ay);       \
        az = fmaf(u4.z, u4.z, az); aw = fmaf(u4.w, u4.w, aw);       \
        ax = fmaf(u5.x, u5.x, ax); ay = fmaf(u5.y, u5.y, ay);       \
        az = fmaf(u5.z, u5.z, az); aw = fmaf(u5.w, u5.w, aw);       \
        ax = fmaf(u6.x, u6.x, ax); ay = fmaf(u6.y, u6.y, ay);       \
        az = fmaf(u6.z, u6.z, az); aw = fmaf(u6.w, u6.w, aw);       \
        ax = fmaf(u7.x, u7.x, ax); ay = fmaf(u7.y, u7.y, ay);       \
        az = fmaf(u7.z, u7.z, az); aw = fmaf(u7.w, u7.w, aw);       \
    } while (0)

// No min-blocks clause: register count floats (expect ~90), so ptxas can keep
// 16 LDG.128 in flight per thread. One 512-thread block always fits per SM,
// so all 148 blocks are co-resident -> software grid barrier is safe.
__global__ __launch_bounds__(512) void semidef_kernel(
    const float4* __restrict__ Y, float* __restrict__ out)
{
    const int tid = threadIdx.x;                        // 0..511
    const unsigned int b = blockIdx.x;

    // Balanced static slab range: blocks [0,124) take 14 slabs, rest 13.
    const int nslabs = (b < SLAB_REM) ? (SLAB_BASE + 1) : SLAB_BASE;
    const long start = (long)b * SLAB_BASE + (long)min(b, (unsigned int)SLAB_REM);

    // ---- Phase 1: streaming, two slabs (16 rows) per iteration ----
    float ax = 0.f, ay = 0.f, az = 0.f, aw = 0.f;
    int i = 0;
    for (; i + 2 <= nslabs; i += 2) {
        const float4* __restrict__ p0 =
            Y + (start + i) * ROWS_PER_SLAB * COLS4 + tid;
        const float4* __restrict__ p1 = p0 + ROWS_PER_SLAB * COLS4;
        // 16 independent LDG.128 in flight.
        SQACC8(p0);
        SQACC8(p1);
    }
    if (i < nslabs) {
        const float4* __restrict__ p0 =
            Y + (start + i) * ROWS_PER_SLAB * COLS4 + tid;
        SQACC8(p0);
    }
    float4 acc; acc.x = ax; acc.y = ay; acc.z = az; acc.w = aw;
    g_partial[(long)b * COLS4 + tid] = acc;

    // Zero the scalar output before any phase-2 atomicAdd; ordered by the
    // fence + grid barrier below.
    if (b == 0 && tid == 0) out[0] = 0.0f;

    // ---- Software grid barrier ----
    __threadfence();
    __syncthreads();
    if (tid == 0) {
        atomicAdd(&g_done, 1u);
        volatile unsigned int* vd = &g_done;
        while (*vd < GRID1) { }
    }
    __syncthreads();

    // ---- Phase 2: blocks [0,128) reduce 4 f4-columns each over 148 rows ----
    if (b < 128) {
        const int fc = tid & 3;                  // 0..3
        const int rg = tid >> 2;                 // 0..127
        const int f4col = (int)b * 4 + fc;       // 0..511

        float4 a = g_partial[(long)rg * COLS4 + f4col];
        if (rg < GRID1 - 128) {                  // fold rows 128..147
            float4 e = g_partial[(long)(rg + 128) * COLS4 + f4col];
            a.x += e.x; a.y += e.y; a.z += e.z; a.w += e.w;
        }

        __shared__ float4 s[512];                // index = rg*4 + fc == tid
        s[tid] = a;
        __syncthreads();

        #pragma unroll
        for (int stride = 64; stride >= 1; stride >>= 1) {
            if (rg < stride) {
                float4 b2 = s[(rg + stride) * 4 + fc];
                float4 a2 = s[tid];
                a2.x += b2.x; a2.y += b2.y; a2.z += b2.z; a2.w += b2.w;
                s[tid] = a2;
            }
            __syncthreads();
        }

        if (tid == 0) {
            const float inv_n = 1.0f / (float)N_ROWS;
            float total = 0.f;
            #pragma unroll
            for (int f = 0; f < 4; f++) {
                float4 d = s[f];
                total += fabsf(1.0f - d.x * inv_n);
                total += fabsf(1.0f - d.y * inv_n);
                total += fabsf(1.0f - d.z * inv_n);
                total += fabsf(1.0f - d.w * inv_n);
            }
            atomicAdd(out, total);
        }
    }

    // Reset counters for the next graph replay: last finishing block only.
    if (tid == 0) {
        unsigned int r2 = atomicAdd(&g_done2, 1u);
        if (r2 == GRID1 - 1) {
            g_done  = 0;
            g_done2 = 0;
        }
    }
}

extern "C" void kernel_launch(void* const* d_in, const int* in_sizes, int n_in,
                              void* d_out, int out_size)
{
    const float4* Y = (const float4*)d_in[0];
    float* out = (float*)d_out;

    semidef_kernel<<<GRID1, 512>>>(Y, out);
}

// round 13
// speedup vs baseline: 1.0703x; 1.0703x over previous
#include <cuda_runtime.h>

// Y: [16384, 2048] fp32, row-major.
// loss = sum_d | 1 - (sum_n Y[n,d]^2) / n |

#define N_ROWS        16384
#define N_COLS        2048
#define COLS4         (N_COLS / 4)               // 512 float4 per row
#define ROWS_PER_SLAB 8
#define N_SLABS       (N_ROWS / ROWS_PER_SLAB)   // 2048 slabs
#define GRID1         296                        // 148 SMs x 2 blocks, one wave
#define SLAB_BASE     (N_SLABS / GRID1)          // 6
#define SLAB_REM      (N_SLABS % GRID1)          // first 272 blocks take 7

#define PROWS         (GRID1 * 2)                // 592 partial rows (2 halves/block)

// Scratch (no cudaMalloc allowed).
__device__ float4       g_partial[PROWS * COLS4];
__device__ unsigned int g_done;    // phase-1 arrival counter
__device__ unsigned int g_done2;   // completion counter (for reset)

// 1024 threads x 2 blocks/SM = 2048 threads/SM (100% occupancy). The (1024,2)
// clause caps regs at 32 — exactly what ptxas picks for this body anyway
// (proven R7/R12), so no MLP is lost and co-residency of all 296 blocks is
// guaranteed -> software grid barrier is deadlock-free.
__global__ __launch_bounds__(1024, 2) void semidef_kernel(
    const float4* __restrict__ Y, float* __restrict__ out)
{
    const int tid  = threadIdx.x;                // 0..1023
    const int col4 = tid & (COLS4 - 1);          // 0..511
    const int half = tid >> 9;                   // 0..1
    const unsigned int b = blockIdx.x;

    // Balanced static slab range: blocks [0,272) take 7 slabs, rest take 6.
    const int nslabs = (b < SLAB_REM) ? (SLAB_BASE + 1) : SLAB_BASE;
    const long start = (long)b * SLAB_BASE + (long)min(b, (unsigned int)SLAB_REM);

    // ---- Phase 1: streaming. Each thread covers 4 rows of its 8-row slab
    //      (rows half*4 .. half*4+3): 4 independent LDG.128 in flight. ----
    float ax = 0.f, ay = 0.f, az = 0.f, aw = 0.f;
    for (int i = 0; i < nslabs; i++) {
        const float4* __restrict__ p =
            Y + (start + i) * ROWS_PER_SLAB * COLS4
              + (long)half * 4 * COLS4 + col4;

        float4 v0 = p[0 * COLS4];
        float4 v1 = p[1 * COLS4];
        float4 v2 = p[2 * COLS4];
        float4 v3 = p[3 * COLS4];

        ax = fmaf(v0.x, v0.x, ax); ay = fmaf(v0.y, v0.y, ay);
        az = fmaf(v0.z, v0.z, az); aw = fmaf(v0.w, v0.w, aw);
        ax = fmaf(v1.x, v1.x, ax); ay = fmaf(v1.y, v1.y, ay);
        az = fmaf(v1.z, v1.z, az); aw = fmaf(v1.w, v1.w, aw);
        ax = fmaf(v2.x, v2.x, ax); ay = fmaf(v2.y, v2.y, ay);
        az = fmaf(v2.z, v2.z, az); aw = fmaf(v2.w, v2.w, aw);
        ax = fmaf(v3.x, v3.x, ax); ay = fmaf(v3.y, v3.y, ay);
        az = fmaf(v3.z, v3.z, az); aw = fmaf(v3.w, v3.w, aw);
    }
    float4 acc; acc.x = ax; acc.y = ay; acc.z = az; acc.w = aw;
    // Partial row = b*2 + half.
    g_partial[((long)b * 2 + half) * COLS4 + col4] = acc;

    // Zero the scalar output before any phase-2 atomicAdd; ordered by the
    // fence + grid barrier below.
    if (b == 0 && tid == 0) out[0] = 0.0f;

    // ---- Software grid barrier ----
    __threadfence();
    __syncthreads();
    if (tid == 0) {
        atomicAdd(&g_done, 1u);
        volatile unsigned int* vd = &g_done;
        while (*vd < GRID1) { }
    }
    __syncthreads();

    // ---- Phase 2: blocks [0,256) reduce 2 f4-columns each over 592 rows ----
    if (b < 256) {
        const int fc = tid & 1;                  // 0..1
        const int rg = tid >> 1;                 // 0..511
        const int f4col = (int)b * 2 + fc;       // 0..511

        float4 a = g_partial[(long)rg * COLS4 + f4col];
        if (rg < PROWS - 512) {                  // fold rows 512..591
            float4 e = g_partial[(long)(rg + 512) * COLS4 + f4col];
            a.x += e.x; a.y += e.y; a.z += e.z; a.w += e.w;
        }

        __shared__ float4 s[1024];               // index = rg*2 + fc == tid
        s[tid] = a;
        __syncthreads();

        #pragma unroll
        for (int stride = 256; stride >= 1; stride >>= 1) {
            if (rg < stride) {
                float4 b2 = s[(rg + stride) * 2 + fc];
                float4 a2 = s[tid];
                a2.x += b2.x; a2.y += b2.y; a2.z += b2.z; a2.w += b2.w;
                s[tid] = a2;
            }
            __syncthreads();
        }

        if (tid == 0) {
            const float inv_n = 1.0f / (float)N_ROWS;
            float total = 0.f;
            #pragma unroll
            for (int f = 0; f < 2; f++) {
                float4 d = s[f];
                total += fabsf(1.0f - d.x * inv_n);
                total += fabsf(1.0f - d.y * inv_n);
                total += fabsf(1.0f - d.z * inv_n);
                total += fabsf(1.0f - d.w * inv_n);
            }
            atomicAdd(out, total);
        }
    }

    // Reset counters for the next graph replay: last finishing block only.
    if (tid == 0) {
        unsigned int r2 = atomicAdd(&g_done2, 1u);
        if (r2 == GRID1 - 1) {
            g_done  = 0;
            g_done2 = 0;
        }
    }
}

extern "C" void kernel_launch(void* const* d_in, const int* in_sizes, int n_in,
                              void* d_out, int out_size)
{
    const float4* Y = (const float4*)d_in[0];
    float* out = (float*)d_out;

    semidef_kernel<<<GRID1, 1024>>>(Y, out);
}